// round 10
// baseline (speedup 1.0000x reference)
#include <cuda_runtime.h>
#include <cuda_bf16.h>
#include <math.h>
#include <stdint.h>

#define S_LEN 512
#define BATCH 64
#define HID 512
#define TAGS 50
#define K2 2500             // TAGS*TAGS
#define K2PH 2512           // padded row in halfs (5024 B, 16B mult)
#define START_TAG 48
#define END_TAG 49
#define M_TOT (S_LEN*BATCH) // 32768
#define NTILES 20           // ceil(2500/128)
#define NPAD (NTILES*128)   // 2560

// Scratch (no allocations allowed)
// E is stored PERMUTED: column index n' = j*50 + i  (i = "from" tag, j = "to" tag)
__device__ __align__(1024) unsigned short g_Eh[(size_t)M_TOT * K2PH];   // bf16 E', ~165 MB
__device__ __align__(1024) unsigned char g_A8[(size_t)M_TOT * HID];     // e4m3 feats, tiled (16 MB)
__device__ __align__(1024) unsigned char g_W8[(size_t)NPAD * HID];      // e4m3 W', tiled+permuted
__device__ float g_tg[M_TOT];
__device__ int g_t64;   // target stored as int64 (vs int32)
__device__ int g_m32;   // mask stored as int32 (vs bool/byte)

// ===========================================================================
// PTX helpers
// ===========================================================================
__device__ __forceinline__ uint32_t smem_u32(const void* p) {
    uint32_t a;
    asm("{ .reg .u64 t; cvta.to.shared.u64 t, %1; cvt.u32.u64 %0, t; }" : "=r"(a) : "l"(p));
    return a;
}
#define MBAR_INIT(addr, cnt) \
    asm volatile("mbarrier.init.shared.b64 [%0], %1;" :: "r"(addr), "r"(cnt) : "memory")
#define MBAR_EXPECT_TX(addr, bytes) \
    asm volatile("mbarrier.arrive.expect_tx.shared.b64 _, [%0], %1;" :: "r"(addr), "r"(bytes) : "memory")
#define MBAR_WAIT(addr, par) do {                                              \
    uint32_t _m = (addr), _p = (par), _d;                                      \
    asm volatile("{\n\t.reg .pred p;\n\t"                                      \
        "mbarrier.try_wait.parity.acquire.cta.shared::cta.b64 p, [%1], %2;\n\t"\
        "selp.b32 %0, 1, 0, p;\n\t}" : "=r"(_d) : "r"(_m), "r"(_p) : "memory");\
    if (!_d) {                                                                 \
        asm volatile("{\n\t.reg .pred P1;\n\t"                                 \
            "W%=:\n\t"                                                         \
            "mbarrier.try_wait.parity.acquire.cta.shared::cta.b64 P1, [%0], %1, 0x989680;\n\t" \
            "@P1 bra.uni D%=;\n\t"                                             \
            "bra.uni W%=;\n\t"                                                 \
            "D%=:\n\t}" :: "r"(_m), "r"(_p) : "memory");                       \
    }                                                                          \
} while (0)
#define BULK_G2S(dst, src, bytes, bar) \
    asm volatile("cp.async.bulk.shared::cta.global.mbarrier::complete_tx::bytes [%0], [%1], %2, [%3];" \
        :: "r"(dst), "l"(src), "r"(bytes), "r"(bar) : "memory")

__device__ __forceinline__ uint32_t pack_bf16x2(float lo, float hi) {
    uint32_t r;
    asm("cvt.rn.bf16x2.f32 %0, %1, %2;" : "=r"(r) : "f"(hi), "f"(lo));
    return r;
}
__device__ __forceinline__ float bf2f(unsigned short u) {
    return __uint_as_float(((unsigned int)u) << 16);
}
// Pack 4 floats -> 4 e4m3 bytes (k ascending = byte ascending)
__device__ __forceinline__ uint32_t pack_e4m3x4(float f0, float f1, float f2, float f3) {
    unsigned short lo, hi;
    asm("cvt.rn.satfinite.e4m3x2.f32 %0, %1, %2;" : "=h"(lo) : "f"(f1), "f"(f0));
    asm("cvt.rn.satfinite.e4m3x2.f32 %0, %1, %2;" : "=h"(hi) : "f"(f3), "f"(f2));
    uint32_t r;
    asm("mov.b32 %0, {%1, %2};" : "=r"(r) : "h"(lo), "h"(hi));
    return r;
}
// FFMA-only exp (rel err <= 4.2e-5)
__device__ __forceinline__ float fast_exp(float x) {
    float z = __fmul_rn(x, 1.44269504f);
    float t = __fadd_rn(z, 12582912.0f);
    float n = __fadd_rn(t, -12582912.0f);
    float f = __fadd_rn(z, -n);
    float p = 0.00961812910f;
    p = fmaf(p, f, 0.05550410866f);
    p = fmaf(p, f, 0.24022650696f);
    p = fmaf(p, f, 0.69314718056f);
    p = fmaf(p, f, 1.0f);
    return __int_as_float(__float_as_int(p) + (__float_as_int(t) << 23));
}
__device__ __forceinline__ void mma_fp8(float& d0, float& d1, float& d2, float& d3,
                                        uint32_t a0, uint32_t a1, uint32_t a2, uint32_t a3,
                                        uint32_t b0, uint32_t b1) {
    asm volatile(
        "mma.sync.aligned.m16n8k32.row.col.f32.e4m3.e4m3.f32 "
        "{%0,%1,%2,%3},{%4,%5,%6,%7},{%8,%9},{%0,%1,%2,%3};"
        : "+f"(d0), "+f"(d1), "+f"(d2), "+f"(d3)
        : "r"(a0), "r"(a1), "r"(a2), "r"(a3), "r"(b0), "r"(b1));
}

// ===========================================================================
// Kernel 0: zero output + detect input storage widths
// ===========================================================================
__global__ void init_kernel(float* out, const void* target, const void* mask) {
    if (threadIdx.x == 0) {
        out[0] = 0.0f;
        const unsigned int* tw = (const unsigned int*)target;
        unsigned int nz = 0;
#pragma unroll
        for (int q = 0; q < 64; q++) nz |= tw[2 * q + 1];
        g_t64 = (nz == 0) ? 1 : 0;
        const unsigned int* mw = (const unsigned int*)mask;
        unsigned int big = 0;
#pragma unroll
        for (int q = 0; q < 64; q++) big |= (mw[q] > 1u) ? 1u : 0u;
        g_m32 = big ? 0 : 1;
    }
}
__device__ __forceinline__ bool mask_at(const void* mask, int idx) {
    if (g_m32) return ((const int*)mask)[idx] != 0;
    return ((const unsigned char*)mask)[idx] != 0;
}

// ===========================================================================
// Kernel 0b: convert feats -> e4m3 tiles; W -> e4m3 PERMUTED tiles.
// Tile = 128 rows x 64 k-bytes = 8 KB contiguous; 8 chunks per row-tile.
// W' row n' = j*50+i  reads W row i*50+j  (n' >= 2500 -> zeros).
// ===========================================================================
__global__ __launch_bounds__(256) void cvt_kernel(
    const float* __restrict__ A, const float* __restrict__ W)
{
    const int stride = gridDim.x * blockDim.x;
    unsigned int* A8 = (unsigned int*)g_A8;
    unsigned int* W8 = (unsigned int*)g_W8;
    // A: M_TOT rows x 128 float4-groups
    for (int id = blockIdx.x * blockDim.x + threadIdx.x; id < M_TOT * 128; id += stride) {
        int m = id >> 7, kq = id & 127;
        float4 v = ((const float4*)A)[id];
        uint32_t u = pack_e4m3x4(v.x, v.y, v.z, v.w);
        int tile = m >> 7, chunk = kq >> 4;
        A8[(size_t)tile * (8 * 128 * 16) + chunk * (128 * 16) + (m & 127) * 16 + (kq & 15)] = u;
    }
    // W': NPAD rows x 128 float4-groups
    for (int id = blockIdx.x * blockDim.x + threadIdx.x; id < NPAD * 128; id += stride) {
        int np = id >> 7, kq = id & 127;
        uint32_t u = 0;
        if (np < K2) {
            int orig = (np % TAGS) * TAGS + np / TAGS;   // W row i*50+j for n'=j*50+i
            float4 v = ((const float4*)W)[orig * 128 + kq];
            u = pack_e4m3x4(v.x, v.y, v.z, v.w);
        }
        int tile = np >> 7, chunk = kq >> 4;
        W8[(size_t)tile * (8 * 128 * 16) + chunk * (128 * 16) + (np & 127) * 16 + (kq & 15)] = u;
    }
}

// ===========================================================================
// Kernel 1: fp8 mma.sync GEMM + fast-exp epilogue -> g_Eh (bf16, permuted cols)
// BM=BN=128, k chunks of 64 fp8. 256 threads, warp grid 2(m)x4(n).
// Fills: 2 cp.async.bulk (8KB each) per chunk, double-buffered.
// k-permutation trick: thread t's 16B at offset 16t covers both k32 steps;
// slot->phys bijection identical on A and B => result exact.
// ===========================================================================
#define NCHUNK 8
#define TILEB 8192
#define BUFSZ (2*TILEB)                 // 16 KB per buffer
#define RPH 136                         // staging row stride in halfs
#define STAGEBYTES (128 * RPH * 2)      // 34816
#define GEMM_SMEM (STAGEBYTES + 1024)

__global__ __launch_bounds__(256, 2) void gemm_tc_kernel(const float* __restrict__ bias)
{
    extern __shared__ char smem[];
    const uint32_t sbase = smem_u32(smem);
    const int tid = threadIdx.x;
    const int nt0 = blockIdx.x;
    const int mt0 = blockIdx.y;
    const int n0 = nt0 * 128;
    const int m0 = mt0 * 128;
    float* sbias = (float*)(smem + STAGEBYTES);
    const uint32_t mb = sbase + STAGEBYTES + 512;

    if (tid < 128) {
        int np = n0 + tid;
        sbias[tid] = (np < K2) ? bias[(np % TAGS) * TAGS + np / TAGS] : 0.0f;
    }
    if (tid == 0) { MBAR_INIT(mb, 1); MBAR_INIT(mb + 8, 1); }
    __syncthreads();

    const char* gA = (const char*)g_A8 + (size_t)mt0 * NCHUNK * TILEB;
    const char* gW = (const char*)g_W8 + (size_t)nt0 * NCHUNK * TILEB;

    auto issue = [&](int c) {
        const int buf = c & 1;
        const uint32_t bar = mb + 8 * buf;
        MBAR_EXPECT_TX(bar, 2 * TILEB);
        BULK_G2S(sbase + buf * BUFSZ,         gA + (size_t)c * TILEB, TILEB, bar);
        BULK_G2S(sbase + buf * BUFSZ + TILEB, gW + (size_t)c * TILEB, TILEB, bar);
    };
    if (tid == 0) issue(0);

    const int w = tid >> 5;
    const int lane = tid & 31;
    const int g = lane >> 2;
    const int t = lane & 3;
    const int wm = w >> 2;         // 0..1
    const int wn = w & 3;          // 0..3

    float acc[4][4][4];
#pragma unroll
    for (int i = 0; i < 4; i++)
#pragma unroll
        for (int j = 0; j < 4; j++)
#pragma unroll
            for (int q = 0; q < 4; q++) acc[i][j][q] = 0.0f;

    for (int c = 0; c < NCHUNK; c++) {
        if (tid == 0 && c + 1 < NCHUNK) issue(c + 1);
        MBAR_WAIT(mb + 8 * (c & 1), (c >> 1) & 1);

        const char* sA = smem + (c & 1) * BUFSZ;
        const char* sB = sA + TILEB;

        uint4 bfr[4];
#pragma unroll
        for (int nt = 0; nt < 4; nt++)
            bfr[nt] = *(const uint4*)(sB + (wn * 32 + nt * 8 + g) * 64 + t * 16);
#pragma unroll
        for (int i = 0; i < 4; i++) {
            const int ra = wm * 64 + i * 16 + g;
            uint4 a0 = *(const uint4*)(sA + ra * 64 + t * 16);
            uint4 a1 = *(const uint4*)(sA + (ra + 8) * 64 + t * 16);
#pragma unroll
            for (int nt = 0; nt < 4; nt++) {
                mma_fp8(acc[i][nt][0], acc[i][nt][1], acc[i][nt][2], acc[i][nt][3],
                        a0.x, a1.x, a0.y, a1.y, bfr[nt].x, bfr[nt].y);
                mma_fp8(acc[i][nt][0], acc[i][nt][1], acc[i][nt][2], acc[i][nt][3],
                        a0.z, a1.z, a0.w, a1.w, bfr[nt].z, bfr[nt].w);
            }
        }
        __syncthreads();
    }

    // ---- epilogue: E = bf16(fast_exp(D + bias)) into padded SMEM stage ----
    unsigned short* stg = (unsigned short*)smem;
#pragma unroll
    for (int i = 0; i < 4; i++) {
        const int rloc = wm * 64 + i * 16 + g;
#pragma unroll
        for (int nt = 0; nt < 4; nt++) {
            const int cloc = wn * 32 + nt * 8 + 2 * t;
            const float bz0 = sbias[cloc], bz1 = sbias[cloc + 1];
            unsigned int u0 = pack_bf16x2(fast_exp(acc[i][nt][0] + bz0),
                                          fast_exp(acc[i][nt][1] + bz1));
            unsigned int u1 = pack_bf16x2(fast_exp(acc[i][nt][2] + bz0),
                                          fast_exp(acc[i][nt][3] + bz1));
            *(unsigned int*)&stg[rloc * RPH + cloc] = u0;
            *(unsigned int*)&stg[(rloc + 8) * RPH + cloc] = u1;
        }
    }
    __syncthreads();

    // ---- coalesced store-out ----
#pragma unroll
    for (int it = 0; it < 8; it++) {
        int u = tid + it * 256;
        int r = u >> 4;
        int sg = u & 15;
        int colh = sg * 8;
        if (n0 + colh + 8 <= K2PH) {
            uint4 v = *(const uint4*)&stg[r * RPH + colh];
            *(uint4*)&g_Eh[(size_t)(m0 + r) * K2PH + n0 + colh] = v;
        }
    }
}

// ===========================================================================
// Kernel 2: per-position target energy (one warp per position, exact fp32)
// ===========================================================================
__global__ __launch_bounds__(256) void tg_kernel(
    const float* __restrict__ feats, const float* __restrict__ W,
    const float* __restrict__ bias, const void* __restrict__ target,
    const void* __restrict__ mask)
{
    const int warp = (blockIdx.x * blockDim.x + threadIdx.x) >> 5;
    const int lane = threadIdx.x & 31;
    if (warp >= M_TOT) return;

    long long t;
    if (g_t64) t = ((const long long*)target)[warp];
    else       t = (long long)((const int*)target)[warp];

    const float4* a  = (const float4*)(feats + (size_t)warp * HID);
    const float4* w4 = (const float4*)(W + (size_t)t * HID);
    float s = 0.0f;
#pragma unroll
    for (int u = 0; u < 4; u++) {
        float4 av = a[lane + u * 32];
        float4 wv = w4[lane + u * 32];
        s += av.x * wv.x + av.y * wv.y + av.z * wv.z + av.w * wv.w;
    }
#pragma unroll
    for (int off = 16; off; off >>= 1) s += __shfl_xor_sync(0xffffffffu, s, off);
    if (lane == 0)
        g_tg[warp] = mask_at(mask, warp) ? (s + bias[t]) : 0.0f;
}

// ===========================================================================
// Kernel 3: forward scan, one block (64 thr) per batch. ONE sync per step.
// E' layout: thread j reads halfs [j*50 .. j*50+49] contiguously (25 LDS.32).
// Lagged normalization: P_s = qhat_s / y_{s-1}, y_s = qhat_s[0] published in
// double-buffered smem slot; logoff accumulates log(y_{s-1}) on updates.
// ===========================================================================
#define NSTG 8
#define STAGEB (K2PH * 2)    // 5024 bytes per stage

__global__ __launch_bounds__(64) void scan_kernel(
    const void* __restrict__ mask, float* __restrict__ out)
{
    __shared__ __align__(16) unsigned short Es[NSTG][K2PH];
    __shared__ __align__(16) float peb[2][56];
    __shared__ __align__(8) unsigned long long mbar[NSTG];
    __shared__ float y_sh[2];
    __shared__ float s_pend;
    __shared__ float red[2];

    const int b = blockIdx.x;
    const int tid = threadIdx.x;
    const uint32_t mb = smem_u32(mbar);
    const uint32_t esb = smem_u32(Es);

    if (tid == 0) {
#pragma unroll
        for (int q = 0; q < NSTG; q++) MBAR_INIT(mb + 8 * q, 1);
    }
    // init: P_0 = E0 / E0[0];  E0[j] = E'[0,b, j*50+START_TAG]
    float e0 = 0.0f;
    if (tid < TAGS)
        e0 = bf2f(g_Eh[(size_t)b * K2PH + tid * TAGS + START_TAG]);
    float logoff = 0.0f;
    if (tid == 0) { y_sh[0] = e0; logoff = __logf(e0); }
    __syncthreads();
    float myp = 0.0f;
    {
        float r0 = __frcp_rn(y_sh[0]);
        if (tid < TAGS) { myp = e0 * r0; peb[0][tid] = myp; }
    }
    // prefetch stages for s=1..7
    if (tid == 0) {
#pragma unroll
        for (int t = 1; t <= NSTG - 1; t++) {
            int st = (t - 1) & (NSTG - 1);
            MBAR_EXPECT_TX(mb + 8 * st, STAGEB);
            BULK_G2S(esb + st * STAGEB,
                     (const char*)g_Eh + (size_t)(t * BATCH + b) * STAGEB,
                     STAGEB, mb + 8 * st);
        }
    }
    __syncthreads();

    for (int s = 1; s < S_LEN; s++) {
        const int st = (s - 1) & (NSTG - 1);
        const int rd = (s - 1) & 1, wr = s & 1;
        const bool mv = mask_at(mask, s * BATCH + b);   // LDG early, hidden by dot
        if (tid == 0 && s + NSTG - 1 < S_LEN) {
            int ps = (s + NSTG - 2) & (NSTG - 1);
            MBAR_EXPECT_TX(mb + 8 * ps, STAGEB);
            BULK_G2S(esb + ps * STAGEB,
                     (const char*)g_Eh + (size_t)((s + NSTG - 1) * BATCH + b) * STAGEB,
                     STAGEB, mb + 8 * ps);
        }
        const float yprev = y_sh[rd];
        const float rcpy = __frcp_rn(yprev);
        MBAR_WAIT(mb + 8 * st, ((s - 1) >> 3) & 1);

        // load pe vector (50 floats)
        float pr[50];
#pragma unroll
        for (int u = 0; u < 12; u++) {
            float4 v = *(const float4*)&peb[rd][u * 4];
            pr[u * 4 + 0] = v.x; pr[u * 4 + 1] = v.y;
            pr[u * 4 + 2] = v.z; pr[u * 4 + 3] = v.w;
        }
        { float2 v = *(const float2*)&peb[rd][48]; pr[48] = v.x; pr[49] = v.y; }

        float q = 0.0f;
        if (tid < TAGS) {
            const unsigned int* E = (const unsigned int*)((const char*)Es[st] + tid * (TAGS * 2));
            float a0 = 0.0f, a1 = 0.0f, a2 = 0.0f, a3 = 0.0f;
#pragma unroll
            for (int u = 0; u < 24; u += 4) {
                unsigned int e0u = E[u], e1u = E[u + 1], e2u = E[u + 2], e3u = E[u + 3];
                a0 = fmaf(__uint_as_float(e0u << 16), pr[2 * u + 0], a0);
                a1 = fmaf(__uint_as_float(e0u & 0xFFFF0000u), pr[2 * u + 1], a1);
                a2 = fmaf(__uint_as_float(e1u << 16), pr[2 * u + 2], a2);
                a3 = fmaf(__uint_as_float(e1u & 0xFFFF0000u), pr[2 * u + 3], a3);
                a0 = fmaf(__uint_as_float(e2u << 16), pr[2 * u + 4], a0);
                a1 = fmaf(__uint_as_float(e2u & 0xFFFF0000u), pr[2 * u + 5], a1);
                a2 = fmaf(__uint_as_float(e3u << 16), pr[2 * u + 6], a2);
                a3 = fmaf(__uint_as_float(e3u & 0xFFFF0000u), pr[2 * u + 7], a3);
            }
            unsigned int eL = E[24];
            a0 = fmaf(__uint_as_float(eL << 16), pr[48], a0);
            a1 = fmaf(__uint_as_float(eL & 0xFFFF0000u), pr[49], a1);
            q = (a0 + a1) + (a2 + a3);
        }

        if (tid < TAGS) {
            if (mv) myp = q * rcpy;
            peb[wr][tid] = myp;
        }
        if (tid == 0) {
            if (mv) logoff += __logf(yprev);
            y_sh[wr] = mv ? q : yprev;
        }
        __syncthreads();
    }

    // epilogue
    if (tid == END_TAG) s_pend = myp;
    float tg = 0.0f;
    for (int s = tid; s < S_LEN; s += 64) tg += g_tg[s * BATCH + b];
#pragma unroll
    for (int off = 16; off; off >>= 1) tg += __shfl_xor_sync(0xffffffffu, tg, off);
    if ((tid & 31) == 0) red[tid >> 5] = tg;
    __syncthreads();
    if (tid == 0) {
        float tgb = red[0] + red[1];
        // final division used divisor y_{S-1}; its log was added when dividing.
        float pEnd = __logf(s_pend) + logoff;
        atomicAdd(out, (pEnd - tgb) / (float)BATCH);
    }
}

// ===========================================================================
extern "C" void kernel_launch(void* const* d_in, const int* in_sizes, int n_in,
                              void* d_out, int out_size)
{
    const float* feats  = (const float*)d_in[0];
    const float* W      = (const float*)d_in[1];
    const float* bias   = (const float*)d_in[2];
    const void*  target = d_in[3];
    const void*  mask   = (const void*)d_in[4];
    float* out = (float*)d_out;

    cudaFuncSetAttribute(gemm_tc_kernel,
                         cudaFuncAttributeMaxDynamicSharedMemorySize, GEMM_SMEM);

    init_kernel<<<1, 32>>>(out, target, mask);
    cvt_kernel<<<1184, 256>>>(feats, W);

    dim3 ggrid(NTILES, M_TOT / 128);   // 20 x 256
    gemm_tc_kernel<<<ggrid, 256, GEMM_SMEM>>>(bias);

    tg_kernel<<<M_TOT / 8, 256>>>(feats, W, bias, target, mask);

    scan_kernel<<<BATCH, 64>>>(mask, out);
}

// round 12
// speedup vs baseline: 1.0962x; 1.0962x over previous
#include <cuda_runtime.h>
#include <cuda_bf16.h>
#include <math.h>
#include <stdint.h>

#define S_LEN 512
#define BATCH 64
#define HID 512
#define TAGS 50
#define K2 2500             // TAGS*TAGS
#define K2PH 2512           // padded row in halfs (5024 B, 16B mult)
#define START_TAG 48
#define END_TAG 49
#define M_TOT (S_LEN*BATCH) // 32768
#define NTILES 20           // ceil(2500/128)
#define NPAD (NTILES*128)   // 2560

// Scratch (no allocations allowed)
__device__ __align__(1024) unsigned short g_Eh[(size_t)M_TOT * K2PH];      // bf16 E, ~165 MB
__device__ __align__(1024) unsigned int g_Ah[(size_t)M_TOT * HID / 2];     // bf16 feats, tiled
__device__ __align__(1024) unsigned int g_Wh[(size_t)NPAD * HID / 2];      // bf16 W, tiled+padded
__device__ float g_tg[M_TOT];
__device__ int g_t64;   // target stored as int64 (vs int32)
__device__ int g_m32;   // mask stored as int32 (vs bool/byte)

// ===========================================================================
// PTX helpers
// ===========================================================================
__device__ __forceinline__ uint32_t smem_u32(const void* p) {
    uint32_t a;
    asm("{ .reg .u64 t; cvta.to.shared.u64 t, %1; cvt.u32.u64 %0, t; }" : "=r"(a) : "l"(p));
    return a;
}
#define MBAR_INIT(addr, cnt) \
    asm volatile("mbarrier.init.shared.b64 [%0], %1;" :: "r"(addr), "r"(cnt) : "memory")
#define MBAR_EXPECT_TX(addr, bytes) \
    asm volatile("mbarrier.arrive.expect_tx.shared.b64 _, [%0], %1;" :: "r"(addr), "r"(bytes) : "memory")
#define MBAR_WAIT(addr, par) do {                                              \
    uint32_t _m = (addr), _p = (par), _d;                                      \
    asm volatile("{\n\t.reg .pred p;\n\t"                                      \
        "mbarrier.try_wait.parity.acquire.cta.shared::cta.b64 p, [%1], %2;\n\t"\
        "selp.b32 %0, 1, 0, p;\n\t}" : "=r"(_d) : "r"(_m), "r"(_p) : "memory");\
    if (!_d) {                                                                 \
        asm volatile("{\n\t.reg .pred P1;\n\t"                                 \
            "W%=:\n\t"                                                         \
            "mbarrier.try_wait.parity.acquire.cta.shared::cta.b64 P1, [%0], %1, 0x989680;\n\t" \
            "@P1 bra.uni D%=;\n\t"                                             \
            "bra.uni W%=;\n\t"                                                 \
            "D%=:\n\t}" :: "r"(_m), "r"(_p) : "memory");                       \
    }                                                                          \
} while (0)
#define BULK_G2S(dst, src, bytes, bar) \
    asm volatile("cp.async.bulk.shared::cta.global.mbarrier::complete_tx::bytes [%0], [%1], %2, [%3];" \
        :: "r"(dst), "l"(src), "r"(bytes), "r"(bar) : "memory")

__device__ __forceinline__ uint32_t pack_bf16x2(float lo, float hi) {
    uint32_t r;
    asm("cvt.rn.bf16x2.f32 %0, %1, %2;" : "=r"(r) : "f"(hi), "f"(lo));
    return r;
}
__device__ __forceinline__ float bf2f(unsigned short u) {
    return __uint_as_float(((unsigned int)u) << 16);
}
// FFMA-only exp (rel err <= 4.2e-5)
__device__ __forceinline__ float fast_exp(float x) {
    float z = __fmul_rn(x, 1.44269504f);
    float t = __fadd_rn(z, 12582912.0f);
    float n = __fadd_rn(t, -12582912.0f);
    float f = __fadd_rn(z, -n);
    float p = 0.00961812910f;
    p = fmaf(p, f, 0.05550410866f);
    p = fmaf(p, f, 0.24022650696f);
    p = fmaf(p, f, 0.69314718056f);
    p = fmaf(p, f, 1.0f);
    return __int_as_float(__float_as_int(p) + (__float_as_int(t) << 23));
}
__device__ __forceinline__ void mma_bf16(float& d0, float& d1, float& d2, float& d3,
                                         uint32_t a0, uint32_t a1, uint32_t a2, uint32_t a3,
                                         uint32_t b0, uint32_t b1) {
    asm volatile(
        "mma.sync.aligned.m16n8k16.row.col.f32.bf16.bf16.f32 "
        "{%0,%1,%2,%3},{%4,%5,%6,%7},{%8,%9},{%0,%1,%2,%3};"
        : "+f"(d0), "+f"(d1), "+f"(d2), "+f"(d3)
        : "r"(a0), "r"(a1), "r"(a2), "r"(a3), "r"(b0), "r"(b1));
}

// ===========================================================================
// Kernel 0: zero output + detect input storage widths
// ===========================================================================
__global__ void init_kernel(float* out, const void* target, const void* mask) {
    if (threadIdx.x == 0) {
        out[0] = 0.0f;
        const unsigned int* tw = (const unsigned int*)target;
        unsigned int nz = 0;
#pragma unroll
        for (int q = 0; q < 64; q++) nz |= tw[2 * q + 1];
        g_t64 = (nz == 0) ? 1 : 0;
        const unsigned int* mw = (const unsigned int*)mask;
        unsigned int big = 0;
#pragma unroll
        for (int q = 0; q < 64; q++) big |= (mw[q] > 1u) ? 1u : 0u;
        g_m32 = big ? 0 : 1;
    }
}
__device__ __forceinline__ bool mask_at(const void* mask, int idx) {
    if (g_m32) return ((const int*)mask)[idx] != 0;
    return ((const unsigned char*)mask)[idx] != 0;
}

// ===========================================================================
// Kernel 0b: convert feats/W to bf16 AND tile:
// tile = 128 rows x 32 k-halfs = 8 KB contiguous  (layout [rowtile][chunk][row][32h])
// ===========================================================================
__global__ __launch_bounds__(256) void cvt_kernel(
    const float* __restrict__ A, const float* __restrict__ W)
{
    const int stride = gridDim.x * blockDim.x;
    for (int id = blockIdx.x * blockDim.x + threadIdx.x; id < M_TOT * 256; id += stride) {
        int m = id >> 8, kp = id & 255;
        float2 v = ((const float2*)A)[id];
        int tile = (m >> 7) * 16 + (kp >> 4);
        g_Ah[tile * 2048 + (m & 127) * 16 + (kp & 15)] = pack_bf16x2(v.x, v.y);
    }
    for (int id = blockIdx.x * blockDim.x + threadIdx.x; id < NPAD * 256; id += stride) {
        int n = id >> 8, kp = id & 255;
        unsigned int o = 0;
        if (n < K2) {
            float2 v = ((const float2*)W)[id];
            o = pack_bf16x2(v.x, v.y);
        }
        int tile = (n >> 7) * 16 + (kp >> 4);
        g_Wh[tile * 2048 + (n & 127) * 16 + (kp & 15)] = o;
    }
}

// ===========================================================================
// Kernel 1: bf16 mma.sync GEMM + fast-exp epilogue -> g_Eh (bf16)
// BM=BN=128, k chunks of 32. 256 threads, warp grid 2(m)x4(n), warp tile 64x32.
// Fills: 2 cp.async.bulk per chunk, 3-STAGE ring (fills issued 2 chunks ahead,
// the per-chunk __syncthreads guarantees the overwritten stage was consumed).
// Epilogue: fast_exp + padded SMEM staging (overlays stage buffers) + coalesced
// 16B-segment stores.
// ===========================================================================
#define NCHUNK 16
#define TILEB 8192
#define BUFSZ (2*TILEB)                 // A+B per stage (16 KB)
#define NSTAGE 3
#define RPH 136                         // staging row stride in halfs (272 B)
#define STAGEBYTES (128 * RPH * 2)      // 34816 (overlays the 3 stage buffers)
#define BIASOFF (NSTAGE * BUFSZ)        // 49152
#define GEMM_SMEM (BIASOFF + 512 + 64)

__global__ __launch_bounds__(256, 2) void gemm_tc_kernel(const float* __restrict__ bias)
{
    extern __shared__ char smem[];
    const uint32_t sbase = smem_u32(smem);
    const int tid = threadIdx.x;
    const int nt0 = blockIdx.x;        // n tile
    const int mt0 = blockIdx.y;        // m tile
    const int n0 = nt0 * 128;
    const int m0 = mt0 * 128;
    float* sbias = (float*)(smem + BIASOFF);
    const uint32_t mb = sbase + BIASOFF + 512;

    if (tid < 128) {
        int n = n0 + tid;
        sbias[tid] = (n < K2) ? bias[n] : 0.0f;
    }
    if (tid == 0) {
#pragma unroll
        for (int q = 0; q < NSTAGE; q++) MBAR_INIT(mb + 8 * q, 1);
    }
    __syncthreads();

    const char* gA = (const char*)g_Ah + (size_t)mt0 * 16 * TILEB;
    const char* gW = (const char*)g_Wh + (size_t)nt0 * 16 * TILEB;

    auto issue = [&](int c) {
        const int st = c % NSTAGE;
        const uint32_t bar = mb + 8 * st;
        MBAR_EXPECT_TX(bar, 2 * TILEB);
        BULK_G2S(sbase + st * BUFSZ,         gA + (size_t)c * TILEB, TILEB, bar);
        BULK_G2S(sbase + st * BUFSZ + TILEB, gW + (size_t)c * TILEB, TILEB, bar);
    };
    if (tid == 0) { issue(0); issue(1); }

    const int w = tid >> 5;
    const int lane = tid & 31;
    const int g = lane >> 2;       // row within 8
    const int t = lane & 3;        // 16B segment
    const int wm = w >> 2;         // 0..1 -> m offset wm*64
    const int wn = w & 3;          // 0..3 -> n offset wn*32

    float acc[4][4][4];
#pragma unroll
    for (int i = 0; i < 4; i++)
#pragma unroll
        for (int j = 0; j < 4; j++)
#pragma unroll
            for (int q = 0; q < 4; q++) acc[i][j][q] = 0.0f;

    for (int c = 0; c < NCHUNK; c++) {
        // stage (c+2)%3 was consumed during chunk c-1 (sync passed) -> refill now
        if (tid == 0 && c + 2 < NCHUNK) issue(c + 2);
        MBAR_WAIT(mb + 8 * (c % NSTAGE), (c / NSTAGE) & 1);

        const char* sA = smem + (c % NSTAGE) * BUFSZ;
        const char* sB = sA + TILEB;

        uint4 bfr[4];
#pragma unroll
        for (int nt = 0; nt < 4; nt++)
            bfr[nt] = *(const uint4*)(sB + (wn * 32 + nt * 8 + g) * 64 + t * 16);
#pragma unroll
        for (int i = 0; i < 4; i++) {
            const int ra = wm * 64 + i * 16 + g;
            uint4 a0 = *(const uint4*)(sA + ra * 64 + t * 16);
            uint4 a1 = *(const uint4*)(sA + (ra + 8) * 64 + t * 16);
#pragma unroll
            for (int nt = 0; nt < 4; nt++) {
                mma_bf16(acc[i][nt][0], acc[i][nt][1], acc[i][nt][2], acc[i][nt][3],
                         a0.x, a1.x, a0.y, a1.y, bfr[nt].x, bfr[nt].y);
                mma_bf16(acc[i][nt][0], acc[i][nt][1], acc[i][nt][2], acc[i][nt][3],
                         a0.z, a1.z, a0.w, a1.w, bfr[nt].z, bfr[nt].w);
            }
        }
        __syncthreads();   // all warps done with this stage before its refill
    }

    // ---- epilogue: E = bf16(fast_exp(D + bias)) into padded SMEM stage ----
    unsigned short* stg = (unsigned short*)smem;
#pragma unroll
    for (int i = 0; i < 4; i++) {
        const int rloc = wm * 64 + i * 16 + g;
#pragma unroll
        for (int nt = 0; nt < 4; nt++) {
            const int cloc = wn * 32 + nt * 8 + 2 * t;
            const float bz0 = sbias[cloc], bz1 = sbias[cloc + 1];
            unsigned int u0 = pack_bf16x2(fast_exp(acc[i][nt][0] + bz0),
                                          fast_exp(acc[i][nt][1] + bz1));
            unsigned int u1 = pack_bf16x2(fast_exp(acc[i][nt][2] + bz0),
                                          fast_exp(acc[i][nt][3] + bz1));
            *(unsigned int*)&stg[rloc * RPH + cloc] = u0;
            *(unsigned int*)&stg[(rloc + 8) * RPH + cloc] = u1;
        }
    }
    __syncthreads();

    // ---- coalesced store-out: 2048 16B segments, 2 full rows per warp instr ----
#pragma unroll
    for (int it = 0; it < 8; it++) {
        int u = tid + it * 256;
        int r = u >> 4;            // 0..127
        int sg = u & 15;           // 16B segment within row
        int colh = sg * 8;         // half index within row
        if (n0 + colh + 8 <= K2PH) {
            uint4 v = *(const uint4*)&stg[r * RPH + colh];
            *(uint4*)&g_Eh[(size_t)(m0 + r) * K2PH + n0 + colh] = v;
        }
    }
}

// ===========================================================================
// Kernel 2: per-position target energy (one warp per position, exact fp32)
// ===========================================================================
__global__ __launch_bounds__(256) void tg_kernel(
    const float* __restrict__ feats, const float* __restrict__ W,
    const float* __restrict__ bias, const void* __restrict__ target,
    const void* __restrict__ mask)
{
    const int warp = (blockIdx.x * blockDim.x + threadIdx.x) >> 5;
    const int lane = threadIdx.x & 31;
    if (warp >= M_TOT) return;

    long long t;
    if (g_t64) t = ((const long long*)target)[warp];
    else       t = (long long)((const int*)target)[warp];

    const float4* a  = (const float4*)(feats + (size_t)warp * HID);
    const float4* w4 = (const float4*)(W + (size_t)t * HID);
    float s = 0.0f;
#pragma unroll
    for (int u = 0; u < 4; u++) {
        float4 av = a[lane + u * 32];
        float4 wv = w4[lane + u * 32];
        s += av.x * wv.x + av.y * wv.y + av.z * wv.z + av.w * wv.w;
    }
#pragma unroll
    for (int off = 16; off; off >>= 1) s += __shfl_xor_sync(0xffffffffu, s, off);
    if (lane == 0)
        g_tg[warp] = mask_at(mask, warp) ? (s + bias[t]) : 0.0f;
}

// ===========================================================================
// Kernel 3: sequential forward scan, one block (64 thr) per batch element.
// Normalized real-domain partition: q_j = sum_i E[i][j]*pe[i]; pe<-q/q0;
// logoff += log(q0). E is bf16; 8-deep bulk-copy ring, prefetch distance 7.
// ===========================================================================
#define NSTG 8
#define STAGEB (K2PH * 2)    // 5024 bytes per stage

__global__ __launch_bounds__(64) void scan_kernel(
    const void* __restrict__ mask, float* __restrict__ out)
{
    __shared__ __align__(16) unsigned short Es[NSTG][K2PH];
    __shared__ __align__(8) unsigned long long mbar[NSTG];
    __shared__ float pe[TAGS];
    __shared__ float s_q0;
    __shared__ float red[2];

    const int b = blockIdx.x;
    const int tid = threadIdx.x;
    const uint32_t mb = smem_u32(mbar);
    const uint32_t esb = smem_u32(Es);

    if (tid == 0) {
#pragma unroll
        for (int q = 0; q < NSTG; q++) MBAR_INIT(mb + 8 * q, 1);
    }
    // init: pe = E0_row / E0_row[0], logoff = log(E0_row[0])
    float e0 = 0.0f;
    if (tid < TAGS)
        e0 = bf2f(g_Eh[(size_t)b * K2PH + START_TAG * TAGS + tid]);
    if (tid == 0) s_q0 = e0;
    __syncthreads();
    float logoff = 0.0f;
    if (tid == 0) logoff = __logf(s_q0);
    if (tid < TAGS) pe[tid] = e0 / s_q0;
    __syncthreads();

    if (tid == 0) {
#pragma unroll
        for (int t = 1; t <= NSTG - 1; t++) {
            int st = (t - 1) & (NSTG - 1);
            MBAR_EXPECT_TX(mb + 8 * st, STAGEB);
            BULK_G2S(esb + st * STAGEB,
                     (const char*)g_Eh + (size_t)(t * BATCH + b) * STAGEB,
                     STAGEB, mb + 8 * st);
        }
    }

    for (int s = 1; s < S_LEN; s++) {
        const int st = (s - 1) & (NSTG - 1);
        if (tid == 0 && s + NSTG - 1 < S_LEN) {
            int ps = (s + NSTG - 2) & (NSTG - 1);
            MBAR_EXPECT_TX(mb + 8 * ps, STAGEB);
            BULK_G2S(esb + ps * STAGEB,
                     (const char*)g_Eh + (size_t)((s + NSTG - 1) * BATCH + b) * STAGEB,
                     STAGEB, mb + 8 * ps);
        }
        MBAR_WAIT(mb + 8 * st, ((s - 1) >> 3) & 1);

        float q = 0.0f;
        if (tid < TAGS) {
            const unsigned short* E = Es[st];
            float a0 = 0.0f, a1 = 0.0f, a2 = 0.0f, a3 = 0.0f;
#pragma unroll
            for (int i = 0; i < 48; i += 4) {
                a0 = fmaf(bf2f(E[(i + 0) * TAGS + tid]), pe[i + 0], a0);
                a1 = fmaf(bf2f(E[(i + 1) * TAGS + tid]), pe[i + 1], a1);
                a2 = fmaf(bf2f(E[(i + 2) * TAGS + tid]), pe[i + 2], a2);
                a3 = fmaf(bf2f(E[(i + 3) * TAGS + tid]), pe[i + 3], a3);
            }
            a0 = fmaf(bf2f(E[48 * TAGS + tid]), pe[48], a0);
            a1 = fmaf(bf2f(E[49 * TAGS + tid]), pe[49], a1);
            q = (a0 + a1) + (a2 + a3);
            if (tid == 0) s_q0 = q;
        }
        const bool m = mask_at(mask, s * BATCH + b);
        __syncthreads();            // pe reads done + s_q0 visible
        if (m) {
            if (tid < TAGS) pe[tid] = __fdividef(q, s_q0);
            if (tid == 0) logoff += __logf(s_q0);
        }
        __syncthreads();            // pe writes done before next step
    }

    // epilogue: loss contribution = log(pe[END]) + logoff - sum_s tg[s,b]
    float tg = 0.0f;
    for (int s = tid; s < S_LEN; s += 64) tg += g_tg[s * BATCH + b];
#pragma unroll
    for (int off = 16; off; off >>= 1) tg += __shfl_xor_sync(0xffffffffu, tg, off);
    if ((tid & 31) == 0) red[tid >> 5] = tg;
    __syncthreads();
    if (tid == 0) {
        float tgb = red[0] + red[1];
        float pEnd = __logf(pe[END_TAG]) + logoff;
        atomicAdd(out, (pEnd - tgb) / (float)BATCH);
    }
}

// ===========================================================================
extern "C" void kernel_launch(void* const* d_in, const int* in_sizes, int n_in,
                              void* d_out, int out_size)
{
    const float* feats  = (const float*)d_in[0];
    const float* W      = (const float*)d_in[1];
    const float* bias   = (const float*)d_in[2];
    const void*  target = d_in[3];
    const void*  mask   = (const void*)d_in[4];
    float* out = (float*)d_out;

    cudaFuncSetAttribute(gemm_tc_kernel,
                         cudaFuncAttributeMaxDynamicSharedMemorySize, GEMM_SMEM);

    init_kernel<<<1, 32>>>(out, target, mask);
    cvt_kernel<<<1184, 256>>>(feats, W);

    // tg moved BEFORE gemm (independent) so the ncu capture slot that has been
    // landing on tg now lands on the GEMM kernel.
    tg_kernel<<<M_TOT / 8, 256>>>(feats, W, bias, target, mask);

    dim3 ggrid(NTILES, M_TOT / 128);   // 20 x 256
    gemm_tc_kernel<<<ggrid, 256, GEMM_SMEM>>>(bias);

    scan_kernel<<<BATCH, 64>>>(mask, out);
}

// round 13
// speedup vs baseline: 1.3837x; 1.2623x over previous
#include <cuda_runtime.h>
#include <cuda_bf16.h>
#include <math.h>
#include <stdint.h>

#define S_LEN 512
#define BATCH 64
#define HID 512
#define TAGS 50
#define K2 2500             // TAGS*TAGS
#define K2PH 2512           // padded row in halfs (5024 B, 16B mult)
#define START_TAG 48
#define END_TAG 49
#define M_TOT (S_LEN*BATCH) // 32768
#define NTILES 20           // ceil(2500/128)
#define NPAD (NTILES*128)   // 2560

// Scratch (no allocations allowed)
// E is stored PERMUTED: column n' = j*50 + i  <=>  E'[b,s,n'] = exp(score[s,b,i,j])
__device__ __align__(1024) unsigned short g_Eh[(size_t)M_TOT * K2PH];      // bf16 E', ~165 MB
__device__ __align__(1024) unsigned int g_Ah[(size_t)M_TOT * HID / 2];     // bf16 feats, tiled
__device__ __align__(1024) unsigned int g_Wh[(size_t)NPAD * HID / 2];      // bf16 W', tiled+permuted
__device__ float g_tg[M_TOT];
__device__ int g_t64;   // target stored as int64 (vs int32)
__device__ int g_m32;   // mask stored as int32 (vs bool/byte)

// ===========================================================================
// PTX helpers
// ===========================================================================
__device__ __forceinline__ uint32_t smem_u32(const void* p) {
    uint32_t a;
    asm("{ .reg .u64 t; cvta.to.shared.u64 t, %1; cvt.u32.u64 %0, t; }" : "=r"(a) : "l"(p));
    return a;
}
#define MBAR_INIT(addr, cnt) \
    asm volatile("mbarrier.init.shared.b64 [%0], %1;" :: "r"(addr), "r"(cnt) : "memory")
#define MBAR_EXPECT_TX(addr, bytes) \
    asm volatile("mbarrier.arrive.expect_tx.shared.b64 _, [%0], %1;" :: "r"(addr), "r"(bytes) : "memory")
#define MBAR_WAIT(addr, par) do {                                              \
    uint32_t _m = (addr), _p = (par), _d;                                      \
    asm volatile("{\n\t.reg .pred p;\n\t"                                      \
        "mbarrier.try_wait.parity.acquire.cta.shared::cta.b64 p, [%1], %2;\n\t"\
        "selp.b32 %0, 1, 0, p;\n\t}" : "=r"(_d) : "r"(_m), "r"(_p) : "memory");\
    if (!_d) {                                                                 \
        asm volatile("{\n\t.reg .pred P1;\n\t"                                 \
            "W%=:\n\t"                                                         \
            "mbarrier.try_wait.parity.acquire.cta.shared::cta.b64 P1, [%0], %1, 0x989680;\n\t" \
            "@P1 bra.uni D%=;\n\t"                                             \
            "bra.uni W%=;\n\t"                                                 \
            "D%=:\n\t}" :: "r"(_m), "r"(_p) : "memory");                       \
    }                                                                          \
} while (0)
#define BULK_G2S(dst, src, bytes, bar) \
    asm volatile("cp.async.bulk.shared::cta.global.mbarrier::complete_tx::bytes [%0], [%1], %2, [%3];" \
        :: "r"(dst), "l"(src), "r"(bytes), "r"(bar) : "memory")

__device__ __forceinline__ uint32_t pack_bf16x2(float lo, float hi) {
    uint32_t r;
    asm("cvt.rn.bf16x2.f32 %0, %1, %2;" : "=r"(r) : "f"(hi), "f"(lo));
    return r;
}
__device__ __forceinline__ float bf2f(unsigned short u) {
    return __uint_as_float(((unsigned int)u) << 16);
}
// FFMA-only exp (rel err <= 4.2e-5)
__device__ __forceinline__ float fast_exp(float x) {
    float z = __fmul_rn(x, 1.44269504f);
    float t = __fadd_rn(z, 12582912.0f);
    float n = __fadd_rn(t, -12582912.0f);
    float f = __fadd_rn(z, -n);
    float p = 0.00961812910f;
    p = fmaf(p, f, 0.05550410866f);
    p = fmaf(p, f, 0.24022650696f);
    p = fmaf(p, f, 0.69314718056f);
    p = fmaf(p, f, 1.0f);
    return __int_as_float(__float_as_int(p) + (__float_as_int(t) << 23));
}
__device__ __forceinline__ void mma_bf16(float& d0, float& d1, float& d2, float& d3,
                                         uint32_t a0, uint32_t a1, uint32_t a2, uint32_t a3,
                                         uint32_t b0, uint32_t b1) {
    asm volatile(
        "mma.sync.aligned.m16n8k16.row.col.f32.bf16.bf16.f32 "
        "{%0,%1,%2,%3},{%4,%5,%6,%7},{%8,%9},{%0,%1,%2,%3};"
        : "+f"(d0), "+f"(d1), "+f"(d2), "+f"(d3)
        : "r"(a0), "r"(a1), "r"(a2), "r"(a3), "r"(b0), "r"(b1));
}

// ===========================================================================
// Kernel 0: zero output + detect input storage widths
// ===========================================================================
__global__ void init_kernel(float* out, const void* target, const void* mask) {
    if (threadIdx.x == 0) {
        out[0] = 0.0f;
        const unsigned int* tw = (const unsigned int*)target;
        unsigned int nz = 0;
#pragma unroll
        for (int q = 0; q < 64; q++) nz |= tw[2 * q + 1];
        g_t64 = (nz == 0) ? 1 : 0;
        const unsigned int* mw = (const unsigned int*)mask;
        unsigned int big = 0;
#pragma unroll
        for (int q = 0; q < 64; q++) big |= (mw[q] > 1u) ? 1u : 0u;
        g_m32 = big ? 0 : 1;
    }
}
__device__ __forceinline__ bool mask_at(const void* mask, int idx) {
    if (g_m32) return ((const int*)mask)[idx] != 0;
    return ((const unsigned char*)mask)[idx] != 0;
}

// ===========================================================================
// Kernel 0b: convert feats -> bf16 tiles; W -> bf16 PERMUTED tiles.
// tile = 128 rows x 32 k-halfs = 8 KB contiguous ([rowtile][chunk][row][32h]).
// W' row n' = j*50+i reads W row i*50+j  (n' >= 2500 -> zeros).
// ===========================================================================
__global__ __launch_bounds__(256) void cvt_kernel(
    const float* __restrict__ A, const float* __restrict__ W)
{
    const int stride = gridDim.x * blockDim.x;
    for (int id = blockIdx.x * blockDim.x + threadIdx.x; id < M_TOT * 256; id += stride) {
        int m = id >> 8, kp = id & 255;
        float2 v = ((const float2*)A)[id];
        int tile = (m >> 7) * 16 + (kp >> 4);
        g_Ah[tile * 2048 + (m & 127) * 16 + (kp & 15)] = pack_bf16x2(v.x, v.y);
    }
    for (int id = blockIdx.x * blockDim.x + threadIdx.x; id < NPAD * 256; id += stride) {
        int np = id >> 8, kp = id & 255;
        unsigned int o = 0;
        if (np < K2) {
            int orig = (np % TAGS) * TAGS + np / TAGS;   // W row i*50+j for n'=j*50+i
            float2 v = ((const float2*)W)[orig * 256 + kp];
            o = pack_bf16x2(v.x, v.y);
        }
        int tile = (np >> 7) * 16 + (kp >> 4);
        g_Wh[tile * 2048 + (np & 127) * 16 + (kp & 15)] = o;
    }
}

// ===========================================================================
// Kernel 1: bf16 mma.sync GEMM + fast-exp epilogue -> g_Eh (bf16, permuted cols)
// BM=BN=128, k chunks of 32. 256 threads, warp grid 2(m)x4(n), warp tile 64x32.
// 3-stage cp.async.bulk ring; fast_exp epilogue; SMEM-staged coalesced stores.
// ===========================================================================
#define NCHUNK 16
#define TILEB 8192
#define BUFSZ (2*TILEB)                 // A+B per stage (16 KB)
#define NSTAGE 3
#define RPH 136                         // staging row stride in halfs (272 B)
#define STAGEBYTES (128 * RPH * 2)      // 34816 (overlays the 3 stage buffers)
#define BIASOFF (NSTAGE * BUFSZ)        // 49152
#define GEMM_SMEM (BIASOFF + 512 + 64)

__global__ __launch_bounds__(256, 2) void gemm_tc_kernel(const float* __restrict__ bias)
{
    extern __shared__ char smem[];
    const uint32_t sbase = smem_u32(smem);
    const int tid = threadIdx.x;
    const int nt0 = blockIdx.x;        // n tile
    const int mt0 = blockIdx.y;        // m tile
    const int n0 = nt0 * 128;
    const int m0 = mt0 * 128;
    float* sbias = (float*)(smem + BIASOFF);
    const uint32_t mb = sbase + BIASOFF + 512;

    if (tid < 128) {
        int np = n0 + tid;
        sbias[tid] = (np < K2) ? bias[(np % TAGS) * TAGS + np / TAGS] : 0.0f;
    }
    if (tid == 0) {
#pragma unroll
        for (int q = 0; q < NSTAGE; q++) MBAR_INIT(mb + 8 * q, 1);
    }
    __syncthreads();

    const char* gA = (const char*)g_Ah + (size_t)mt0 * 16 * TILEB;
    const char* gW = (const char*)g_Wh + (size_t)nt0 * 16 * TILEB;

    auto issue = [&](int c) {
        const int st = c % NSTAGE;
        const uint32_t bar = mb + 8 * st;
        MBAR_EXPECT_TX(bar, 2 * TILEB);
        BULK_G2S(sbase + st * BUFSZ,         gA + (size_t)c * TILEB, TILEB, bar);
        BULK_G2S(sbase + st * BUFSZ + TILEB, gW + (size_t)c * TILEB, TILEB, bar);
    };
    if (tid == 0) { issue(0); issue(1); }

    const int w = tid >> 5;
    const int lane = tid & 31;
    const int g = lane >> 2;       // row within 8
    const int t = lane & 3;        // 16B segment
    const int wm = w >> 2;         // 0..1 -> m offset wm*64
    const int wn = w & 3;          // 0..3 -> n offset wn*32

    float acc[4][4][4];
#pragma unroll
    for (int i = 0; i < 4; i++)
#pragma unroll
        for (int j = 0; j < 4; j++)
#pragma unroll
            for (int q = 0; q < 4; q++) acc[i][j][q] = 0.0f;

    for (int c = 0; c < NCHUNK; c++) {
        if (tid == 0 && c + 2 < NCHUNK) issue(c + 2);
        MBAR_WAIT(mb + 8 * (c % NSTAGE), (c / NSTAGE) & 1);

        const char* sA = smem + (c % NSTAGE) * BUFSZ;
        const char* sB = sA + TILEB;

        uint4 bfr[4];
#pragma unroll
        for (int nt = 0; nt < 4; nt++)
            bfr[nt] = *(const uint4*)(sB + (wn * 32 + nt * 8 + g) * 64 + t * 16);
#pragma unroll
        for (int i = 0; i < 4; i++) {
            const int ra = wm * 64 + i * 16 + g;
            uint4 a0 = *(const uint4*)(sA + ra * 64 + t * 16);
            uint4 a1 = *(const uint4*)(sA + (ra + 8) * 64 + t * 16);
#pragma unroll
            for (int nt = 0; nt < 4; nt++) {
                mma_bf16(acc[i][nt][0], acc[i][nt][1], acc[i][nt][2], acc[i][nt][3],
                         a0.x, a1.x, a0.y, a1.y, bfr[nt].x, bfr[nt].y);
                mma_bf16(acc[i][nt][0], acc[i][nt][1], acc[i][nt][2], acc[i][nt][3],
                         a0.z, a1.z, a0.w, a1.w, bfr[nt].z, bfr[nt].w);
            }
        }
        __syncthreads();
    }

    // ---- epilogue: E' = bf16(fast_exp(D + bias')) into padded SMEM stage ----
    unsigned short* stg = (unsigned short*)smem;
#pragma unroll
    for (int i = 0; i < 4; i++) {
        const int rloc = wm * 64 + i * 16 + g;
#pragma unroll
        for (int nt = 0; nt < 4; nt++) {
            const int cloc = wn * 32 + nt * 8 + 2 * t;
            const float bz0 = sbias[cloc], bz1 = sbias[cloc + 1];
            unsigned int u0 = pack_bf16x2(fast_exp(acc[i][nt][0] + bz0),
                                          fast_exp(acc[i][nt][1] + bz1));
            unsigned int u1 = pack_bf16x2(fast_exp(acc[i][nt][2] + bz0),
                                          fast_exp(acc[i][nt][3] + bz1));
            *(unsigned int*)&stg[rloc * RPH + cloc] = u0;
            *(unsigned int*)&stg[(rloc + 8) * RPH + cloc] = u1;
        }
    }
    __syncthreads();

    // ---- coalesced store-out ----
#pragma unroll
    for (int it = 0; it < 8; it++) {
        int u = tid + it * 256;
        int r = u >> 4;
        int sg = u & 15;
        int colh = sg * 8;
        if (n0 + colh + 8 <= K2PH) {
            uint4 v = *(const uint4*)&stg[r * RPH + colh];
            *(uint4*)&g_Eh[(size_t)(m0 + r) * K2PH + n0 + colh] = v;
        }
    }
}

// ===========================================================================
// Kernel 2: per-position target energy (one warp per position, exact fp32)
// ===========================================================================
__global__ __launch_bounds__(256) void tg_kernel(
    const float* __restrict__ feats, const float* __restrict__ W,
    const float* __restrict__ bias, const void* __restrict__ target,
    const void* __restrict__ mask)
{
    const int warp = (blockIdx.x * blockDim.x + threadIdx.x) >> 5;
    const int lane = threadIdx.x & 31;
    if (warp >= M_TOT) return;

    long long t;
    if (g_t64) t = ((const long long*)target)[warp];
    else       t = (long long)((const int*)target)[warp];

    const float4* a  = (const float4*)(feats + (size_t)warp * HID);
    const float4* w4 = (const float4*)(W + (size_t)t * HID);
    float s = 0.0f;
#pragma unroll
    for (int u = 0; u < 4; u++) {
        float4 av = a[lane + u * 32];
        float4 wv = w4[lane + u * 32];
        s += av.x * wv.x + av.y * wv.y + av.z * wv.z + av.w * wv.w;
    }
#pragma unroll
    for (int off = 16; off; off >>= 1) s += __shfl_xor_sync(0xffffffffu, s, off);
    if (lane == 0)
        g_tg[warp] = mask_at(mask, warp) ? (s + bias[t]) : 0.0f;
}

// ===========================================================================
// Kernel 3: sequential forward scan, one block (64 thr) per batch element.
// Permuted E': thread j reads halfs [j*50 .. j*50+49] contiguously (25 LDS.U32).
// Mask preloaded to smem (no per-step LDG). pe loaded to registers at loop top
// (13 broadcast LDS.128, overlapping mbar wait). 2-sync update (R9-proven).
// ===========================================================================
#define NSTG 8
#define STAGEB (K2PH * 2)    // 5024 bytes per stage

__global__ __launch_bounds__(64) void scan_kernel(
    const void* __restrict__ mask, float* __restrict__ out)
{
    __shared__ __align__(16) unsigned short Es[NSTG][K2PH];
    __shared__ __align__(8) unsigned long long mbar[NSTG];
    __shared__ __align__(16) float pe[56];
    __shared__ unsigned char smask[S_LEN];
    __shared__ float s_q0;
    __shared__ float red[2];

    const int b = blockIdx.x;
    const int tid = threadIdx.x;
    const uint32_t mb = smem_u32(mbar);
    const uint32_t esb = smem_u32(Es);

    if (tid == 0) {
#pragma unroll
        for (int q = 0; q < NSTG; q++) MBAR_INIT(mb + 8 * q, 1);
    }
    // preload mask column b into smem (one-time)
    for (int s = tid; s < S_LEN; s += 64)
        smask[s] = mask_at(mask, s * BATCH + b) ? 1 : 0;

    // init: pe = p0 / p0[0];  p0[j] = E'[0,b, j*50+START_TAG]
    float e0 = 0.0f;
    if (tid < TAGS)
        e0 = bf2f(g_Eh[(size_t)b * K2PH + tid * TAGS + START_TAG]);
    if (tid == 0) s_q0 = e0;
    if (tid >= TAGS && tid < 56) pe[tid] = 0.0f;   // pad (never used in dot)
    __syncthreads();
    float logoff = 0.0f;
    if (tid == 0) logoff = __logf(s_q0);
    if (tid < TAGS) pe[tid] = e0 / s_q0;

    // prefetch stages for s=1..7
    if (tid == 0) {
#pragma unroll
        for (int t = 1; t <= NSTG - 1; t++) {
            int st = (t - 1) & (NSTG - 1);
            MBAR_EXPECT_TX(mb + 8 * st, STAGEB);
            BULK_G2S(esb + st * STAGEB,
                     (const char*)g_Eh + (size_t)(t * BATCH + b) * STAGEB,
                     STAGEB, mb + 8 * st);
        }
    }
    __syncthreads();

    for (int s = 1; s < S_LEN; s++) {
        const int st = (s - 1) & (NSTG - 1);
        if (tid == 0 && s + NSTG - 1 < S_LEN) {
            int ps = (s + NSTG - 2) & (NSTG - 1);
            MBAR_EXPECT_TX(mb + 8 * ps, STAGEB);
            BULK_G2S(esb + ps * STAGEB,
                     (const char*)g_Eh + (size_t)((s + NSTG - 1) * BATCH + b) * STAGEB,
                     STAGEB, mb + 8 * ps);
        }

        // pe -> registers (broadcast LDS.128, overlaps the mbar wait below)
        float pr[52];
#pragma unroll
        for (int u = 0; u < 13; u++) {
            float4 v = *(const float4*)&pe[u * 4];
            pr[u * 4 + 0] = v.x; pr[u * 4 + 1] = v.y;
            pr[u * 4 + 2] = v.z; pr[u * 4 + 3] = v.w;
        }
        const bool m = smask[s] != 0;
        MBAR_WAIT(mb + 8 * st, ((s - 1) >> 3) & 1);

        float q = 0.0f;
        if (tid < TAGS) {
            const unsigned int* E =
                (const unsigned int*)((const char*)Es[st] + tid * (TAGS * 2));
            float a0 = 0.0f, a1 = 0.0f, a2 = 0.0f, a3 = 0.0f;
#pragma unroll
            for (int u = 0; u < 24; u += 4) {
                unsigned int e0u = E[u], e1u = E[u + 1], e2u = E[u + 2], e3u = E[u + 3];
                a0 = fmaf(__uint_as_float(e0u << 16), pr[2 * u + 0], a0);
                a1 = fmaf(__uint_as_float(e0u & 0xFFFF0000u), pr[2 * u + 1], a1);
                a2 = fmaf(__uint_as_float(e1u << 16), pr[2 * u + 2], a2);
                a3 = fmaf(__uint_as_float(e1u & 0xFFFF0000u), pr[2 * u + 3], a3);
                a0 = fmaf(__uint_as_float(e2u << 16), pr[2 * u + 4], a0);
                a1 = fmaf(__uint_as_float(e2u & 0xFFFF0000u), pr[2 * u + 5], a1);
                a2 = fmaf(__uint_as_float(e3u << 16), pr[2 * u + 6], a2);
                a3 = fmaf(__uint_as_float(e3u & 0xFFFF0000u), pr[2 * u + 7], a3);
            }
            unsigned int eL = E[24];
            a0 = fmaf(__uint_as_float(eL << 16), pr[48], a0);
            a1 = fmaf(__uint_as_float(eL & 0xFFFF0000u), pr[49], a1);
            q = (a0 + a1) + (a2 + a3);
            if (tid == 0) s_q0 = q;
        }
        __syncthreads();            // E reads done (stage reusable) + s_q0 visible
        if (m) {
            if (tid < TAGS) pe[tid] = __fdividef(q, s_q0);
            if (tid == 0) logoff += __logf(s_q0);
        }
        __syncthreads();            // pe writes done before next step's pr load
    }

    // epilogue: loss contribution = log(pe[END]) + logoff - sum_s tg[s,b]
    float tg = 0.0f;
    for (int s = tid; s < S_LEN; s += 64) tg += g_tg[s * BATCH + b];
#pragma unroll
    for (int off = 16; off; off >>= 1) tg += __shfl_xor_sync(0xffffffffu, tg, off);
    if ((tid & 31) == 0) red[tid >> 5] = tg;
    __syncthreads();
    if (tid == 0) {
        float tgb = red[0] + red[1];
        float pEnd = __logf(pe[END_TAG]) + logoff;
        atomicAdd(out, (pEnd - tgb) / (float)BATCH);
    }
}

// ===========================================================================
extern "C" void kernel_launch(void* const* d_in, const int* in_sizes, int n_in,
                              void* d_out, int out_size)
{
    const float* feats  = (const float*)d_in[0];
    const float* W      = (const float*)d_in[1];
    const float* bias   = (const float*)d_in[2];
    const void*  target = d_in[3];
    const void*  mask   = (const void*)d_in[4];
    float* out = (float*)d_out;

    cudaFuncSetAttribute(gemm_tc_kernel,
                         cudaFuncAttributeMaxDynamicSharedMemorySize, GEMM_SMEM);

    init_kernel<<<1, 32>>>(out, target, mask);
    cvt_kernel<<<1184, 256>>>(feats, W);

    // tg before gemm so the ncu capture slot lands on the GEMM kernel.
    tg_kernel<<<M_TOT / 8, 256>>>(feats, W, bias, target, mask);

    dim3 ggrid(NTILES, M_TOT / 128);   // 20 x 256
    gemm_tc_kernel<<<ggrid, 256, GEMM_SMEM>>>(bias);

    scan_kernel<<<BATCH, 64>>>(mask, out);
}